// round 8
// baseline (speedup 1.0000x reference)
#include <cuda_runtime.h>
#include <math.h>
#include <stdint.h>

// Problem constants
#define NV    5000
#define NFC   10000
#define LAYERS 30
#define NNZT  480000
#define EPSBN 1e-5f

// ---------------- device scratch ----------------
__device__ __align__(16) float g_v [NV  * 128];
__device__ __align__(16) float g_ev[NV  * 128];
__device__ __align__(16) float g_ef[NFC * 128];
__device__ __align__(16) float g_ex[NV  * 128];
__device__ __align__(16) float g_Dv[NFC * 128];
__device__ __align__(16) float g_DA[NV  * 128];
__device__ float g_stats[64 * 512];
__device__ float g_a   [128];
__device__ float g_bout[1];

__device__ __forceinline__ float eluf(float x) {
    return x > 0.f ? x : (__expf(x) - 1.f);
}

__device__ __forceinline__ void tf32split(float x, uint32_t& hi, uint32_t& lo) {
    asm("cvt.rna.tf32.f32 %0, %1;" : "=r"(hi) : "f"(x));
    float d = x - __uint_as_float(hi);
    asm("cvt.rna.tf32.f32 %0, %1;" : "=r"(lo) : "f"(d));
}

__device__ __forceinline__ void mma_tf32(float* d, const uint32_t* a,
                                         uint32_t b0, uint32_t b1) {
    asm volatile(
        "mma.sync.aligned.m16n8k8.row.col.f32.tf32.tf32.f32 "
        "{%0,%1,%2,%3}, {%4,%5,%6,%7}, {%8,%9}, {%0,%1,%2,%3};"
        : "+f"(d[0]), "+f"(d[1]), "+f"(d[2]), "+f"(d[3])
        : "r"(a[0]), "r"(a[1]), "r"(a[2]), "r"(a[3]), "r"(b0), "r"(b1));
}

// ---------------- input projection ----------------
__global__ void k_in(const float* __restrict__ in, const float* __restrict__ Wi,
                     const float* __restrict__ bi, float* __restrict__ statp) {
    int c = threadIdx.x;  // 128
    float w0 = Wi[c], w1 = Wi[128 + c], w2 = Wi[256 + c], b = bi[c];
    float s = 0.f, s2 = 0.f;
    for (int n = blockIdx.x; n < NV; n += gridDim.x) {
        float val = b + in[n * 3] * w0 + in[n * 3 + 1] * w1 + in[n * 3 + 2] * w2;
        g_v [n * 128 + c] = val;
        float e = eluf(val);
        g_ev[n * 128 + c] = e;
        s += e; s2 += e * e;
    }
    atomicAdd(&statp[c], s);
    atomicAdd(&statp[256 + c], s2);
}

// ---------------- COO spMM: 8 threads/edge, float4 vector atomics ----------------
__global__ void k_spmm(const int* __restrict__ rows_, const int* __restrict__ cols_,
                       const float* __restrict__ vals,
                       const float* __restrict__ X, float* __restrict__ Y) {
    int idx = blockIdx.x * blockDim.x + threadIdx.x;
    int e = idx >> 3, d = idx & 7;
    if (e >= NNZT) return;
    int R = rows_[e], Cq = cols_[e];
    float v = vals[e];
    float4 xv = ((const float4*)X)[(Cq >> 2) * 32 + (Cq & 3) * 8 + d];
    float4* yp = (float4*)Y + (R >> 2) * 32 + (R & 3) * 8 + d;
    asm volatile("red.global.add.v4.f32 [%0], {%1,%2,%3,%4};"
                 :: "l"(yp), "f"(v * xv.x), "f"(v * xv.y), "f"(v * xv.z), "f"(v * xv.w)
                 : "memory");
}

// ---------------- column stats over a [rows,128] tensor ----------------
__global__ void k_stats128(const float* __restrict__ X, int rows,
                           float* __restrict__ statp, int off) {
    int c = threadIdx.x;  // 128
    float s = 0.f, s2 = 0.f;
    for (int r = blockIdx.x; r < rows; r += gridDim.x) {
        float x = X[r * 128 + c];
        s += x; s2 += x * x;
    }
    atomicAdd(&statp[off + c], s);
    atomicAdd(&statp[256 + off + c], s2);
}

// ---------------- fused BN + bias-fold + TF32x3 tensor GEMM + elu + stats --------
// out = (A*a) @ W + bias [+ V];  A = [L | R] split pointers, each [rows,128]
// TF32x3: ah*bh + al*bh + ah*bl (fp32-accurate). W split hi/lo once per tile.
template<int KT, bool ACC>
__global__ void __launch_bounds__(256)
k_gemm(const float* __restrict__ L, const float* __restrict__ R, int rows,
       const float* __restrict__ W, const float* __restrict__ bvec,
       const float* __restrict__ gamma, const float* __restrict__ beta,
       const float* __restrict__ statp_in, float invn,
       float* __restrict__ Vout, float* __restrict__ Eout,
       float* __restrict__ statp_out) {
    __shared__ __align__(16) float As  [2][16][72];
    __shared__ __align__(16) float BsH [2][16][136];
    __shared__ __align__(16) float BsL [2][16][136];
    __shared__ float sSc[256];
    __shared__ float sT [256];
    __shared__ float sB [128];
    int tid = threadIdx.x;  // 256

    // prologue: BN fold
    if (KT == 16 || tid < 128) {
        float mean = statp_in[tid] * invn;
        float var  = fmaxf(statp_in[256 + tid] * invn - mean * mean, 0.f);
        float a = gamma[tid] * rsqrtf(var + EPSBN);
        sSc[tid] = a;
        sT[tid]  = beta[tid] - mean * a;
    } else {
        sT[tid] = beta[tid];   // broadcast-avg columns: var==0 -> BN out == beta
    }
    __syncthreads();

    int row0 = blockIdx.x * 64;
    int lane = tid & 31, wid = tid >> 5;
    int wm = wid & 3, wn = wid >> 2;     // warp tile: rows wm*16+, cols wn*64+
    int gq = lane >> 2, tg = lane & 3;   // mma fragment coords
    float acc[8][4];
#pragma unroll
    for (int c = 0; c < 8; c++)
#pragma unroll
        for (int j = 0; j < 4; j++) acc[c][j] = 0.f;
    float biasAcc = 0.f;

    int am = tid >> 2, ak4 = (tid & 3) * 4;   // A loader: 64 rows x 16 k (ALL 256 threads)
    int bk = tid >> 5, bc = (tid & 31) * 4;   // B loader: rows bk, bk+8
    float4 rA, rB0, rB1;

    auto loadRegs = [&](int t) {
        int k0 = t * 16;
        const float* Ab = (KT == 16 && k0 >= 128) ? R : L;
        int r = row0 + am;
        rA = make_float4(0.f, 0.f, 0.f, 0.f);
        if (r < rows) rA = *(const float4*)&Ab[r * 128 + (k0 & 127) + ak4];
        rB0 = *(const float4*)&W[(k0 + bk) * 128 + bc];
        rB1 = *(const float4*)&W[(k0 + 8 + bk) * 128 + bc];
    };
    auto storeSmem = [&](int t, int b) {
        int k0 = t * 16;
        As[b][ak4 + 0][am] = rA.x * sSc[k0 + ak4 + 0];   // all 256 threads: rows 0..63
        As[b][ak4 + 1][am] = rA.y * sSc[k0 + ak4 + 1];
        As[b][ak4 + 2][am] = rA.z * sSc[k0 + ak4 + 2];
        As[b][ak4 + 3][am] = rA.w * sSc[k0 + ak4 + 3];
        uint32_t h, l;
        const float* pb0 = (const float*)&rB0;
        const float* pb1 = (const float*)&rB1;
#pragma unroll
        for (int j = 0; j < 4; j++) {
            tf32split(pb0[j], h, l);
            BsH[b][bk][bc + j] = __uint_as_float(h);
            BsL[b][bk][bc + j] = __uint_as_float(l);
            tf32split(pb1[j], h, l);
            BsH[b][8 + bk][bc + j] = __uint_as_float(h);
            BsL[b][8 + bk][bc + j] = __uint_as_float(l);
        }
    };

    loadRegs(0);
    storeSmem(0, 0);
    __syncthreads();
#pragma unroll 1
    for (int t = 0; t < KT; t++) {
        int b = t & 1;
        if (t + 1 < KT) loadRegs(t + 1);
        if (tid < 128) {   // bias fold on resident W tile (hi+lo == W)
            int k0 = t * 16;
#pragma unroll
            for (int k = 0; k < 16; k++)
                biasAcc += sT[k0 + k] * (BsH[b][k][tid] + BsL[b][k][tid]);
        }
#pragma unroll
        for (int ks = 0; ks < 16; ks += 8) {
            float af0 = As[b][ks + tg    ][wm * 16 + gq];
            float af1 = As[b][ks + tg    ][wm * 16 + gq + 8];
            float af2 = As[b][ks + tg + 4][wm * 16 + gq];
            float af3 = As[b][ks + tg + 4][wm * 16 + gq + 8];
            uint32_t ah[4], al[4];
            tf32split(af0, ah[0], al[0]);
            tf32split(af1, ah[1], al[1]);
            tf32split(af2, ah[2], al[2]);
            tf32split(af3, ah[3], al[3]);
#pragma unroll
            for (int c = 0; c < 8; c++) {
                int n = wn * 64 + c * 8 + gq;
                uint32_t bh0 = __float_as_uint(BsH[b][ks + tg    ][n]);
                uint32_t bh1 = __float_as_uint(BsH[b][ks + tg + 4][n]);
                uint32_t bl0 = __float_as_uint(BsL[b][ks + tg    ][n]);
                uint32_t bl1 = __float_as_uint(BsL[b][ks + tg + 4][n]);
                mma_tf32(acc[c], al, bh0, bh1);
                mma_tf32(acc[c], ah, bl0, bl1);
                mma_tf32(acc[c], ah, bh0, bh1);
            }
        }
        if (t + 1 < KT) storeSmem(t + 1, b ^ 1);
        __syncthreads();
    }

    // KT==8: bias contribution of folded-away W rows 128..255 (t = beta there)
    if (KT == 8 && tid < 128) {
#pragma unroll 4
        for (int c = 128; c < 256; c++) biasAcc += sT[c] * W[c * 128 + tid];
    }
    if (tid < 128) sB[tid] = biasAcc + bvec[tid];
    __syncthreads();

    // epilogue: bias (+accum), elu, stores, per-column stats
    float* red1 = &BsH[0][0][0];
    float* red2 = &BsL[0][0][0];
#pragma unroll
    for (int c = 0; c < 8; c++) {
        int C0 = wn * 64 + c * 8 + tg * 2;
        int R0 = row0 + wm * 16 + gq;
        int R1 = R0 + 8;
        bool ok0 = R0 < rows, ok1 = R1 < rows;
        float e0 = 0.f, e1 = 0.f, e2 = 0.f, e3 = 0.f;
        if (ok0) {
            float v0 = acc[c][0] + sB[C0];
            float v1 = acc[c][1] + sB[C0 + 1];
            if (ACC) {
                float2 old = *(float2*)&Vout[R0 * 128 + C0];
                v0 += old.x; v1 += old.y;
                *(float2*)&Vout[R0 * 128 + C0] = make_float2(v0, v1);
            }
            e0 = eluf(v0); e1 = eluf(v1);
            *(float2*)&Eout[R0 * 128 + C0] = make_float2(e0, e1);
        }
        if (ok1) {
            float v2 = acc[c][2] + sB[C0];
            float v3 = acc[c][3] + sB[C0 + 1];
            if (ACC) {
                float2 old = *(float2*)&Vout[R1 * 128 + C0];
                v2 += old.x; v3 += old.y;
                *(float2*)&Vout[R1 * 128 + C0] = make_float2(v2, v3);
            }
            e2 = eluf(v2); e3 = eluf(v3);
            *(float2*)&Eout[R1 * 128 + C0] = make_float2(e2, e3);
        }
        float s0 = e0 + e2, s1 = e1 + e3;
        float q0 = e0 * e0 + e2 * e2, q1 = e1 * e1 + e3 * e3;
#pragma unroll
        for (int m = 4; m <= 16; m <<= 1) {
            s0 += __shfl_xor_sync(0xffffffffu, s0, m);
            s1 += __shfl_xor_sync(0xffffffffu, s1, m);
            q0 += __shfl_xor_sync(0xffffffffu, q0, m);
            q1 += __shfl_xor_sync(0xffffffffu, q1, m);
        }
        if (gq == 0) {
            red1[wid * 128 + C0]     = s0;
            red1[wid * 128 + C0 + 1] = s1;
            red2[wid * 128 + C0]     = q0;
            red2[wid * 128 + C0 + 1] = q1;
        }
    }
    __syncthreads();
    if (tid < 128) {
        int base = 4 * (tid >> 6);   // the 4 warps covering this column
        float s = red1[(base + 0) * 128 + tid] + red1[(base + 1) * 128 + tid]
                + red1[(base + 2) * 128 + tid] + red1[(base + 3) * 128 + tid];
        atomicAdd(&statp_out[tid], s);
    } else {
        int c = tid - 128;
        int base = 4 * (c >> 6);
        float s = red2[(base + 0) * 128 + c] + red2[(base + 1) * 128 + c]
                + red2[(base + 2) * 128 + c] + red2[(base + 3) * 128 + c];
        atomicAdd(&statp_out[256 + c], s);
    }
}

// ---------------- final head ----------------
__global__ void k_head_prep(const float* __restrict__ gamma, const float* __restrict__ beta,
                            const float* __restrict__ Wout, const float* __restrict__ bout,
                            const float* __restrict__ statp, float invn) {
    __shared__ float sh[128];
    int c = threadIdx.x;  // 128
    float mean = statp[c] * invn;
    float var  = fmaxf(statp[256 + c] * invn - mean * mean, 0.f);
    float a = gamma[c] * rsqrtf(var + EPSBN);
    g_a[c] = a;
    sh[c] = (beta[c] - mean * a) * Wout[c];
    __syncthreads();
    for (int s = 64; s > 0; s >>= 1) {
        if (c < s) sh[c] += sh[c + s];
        __syncthreads();
    }
    if (c == 0) g_bout[0] = bout[0] + sh[0];
}

__global__ void k_final(const float* __restrict__ Wout, float* __restrict__ out) {
    int warp = (blockIdx.x * blockDim.x + threadIdx.x) >> 5;
    int lane = threadIdx.x & 31;
    if (warp >= NV) return;
    float s = 0.f;
#pragma unroll
    for (int q = 0; q < 4; q++) {
        int c = q * 32 + lane;
        s += g_v[warp * 128 + c] * g_a[c] * Wout[c];
    }
#pragma unroll
    for (int o = 16; o; o >>= 1) s += __shfl_xor_sync(0xffffffffu, s, o);
    if (lane == 0) out[warp] = eluf(s + g_bout[0]);
}

// ---------------- host orchestration ----------------
extern "C" void kernel_launch(void* const* d_in, const int* in_sizes, int n_in,
                              void* d_out, int out_size) {
    const float* inputs   = (const float*)d_in[0];
    const int*   Di_rows  = (const int*)d_in[2];
    const int*   Di_cols  = (const int*)d_in[3];
    const float* Di_vals  = (const float*)d_in[4];
    const int*   DiA_rows = (const int*)d_in[5];
    const int*   DiA_cols = (const int*)d_in[6];
    const float* DiA_vals = (const float*)d_in[7];
    const float* W_in  = (const float*)d_in[8];
    const float* b_in  = (const float*)d_in[9];
    const float* g0    = (const float*)d_in[10];
    const float* be0   = (const float*)d_in[11];
    const float* W0    = (const float*)d_in[12];
    const float* b0    = (const float*)d_in[13];
    const float* g1    = (const float*)d_in[14];
    const float* be1   = (const float*)d_in[15];
    const float* Wl1   = (const float*)d_in[16];
    const float* bl1   = (const float*)d_in[17];
    const float* g2    = (const float*)d_in[18];
    const float* be2   = (const float*)d_in[19];
    const float* W_out = (const float*)d_in[20];
    const float* b_out = (const float*)d_in[21];
    float* out = (float*)d_out;
    (void)in_sizes; (void)n_in; (void)out_size;

    float *p_v, *p_ev, *p_ef, *p_ex, *p_Dv, *p_DA, *p_stats;
    cudaGetSymbolAddress((void**)&p_v,     g_v);
    cudaGetSymbolAddress((void**)&p_ev,    g_ev);
    cudaGetSymbolAddress((void**)&p_ef,    g_ef);
    cudaGetSymbolAddress((void**)&p_ex,    g_ex);
    cudaGetSymbolAddress((void**)&p_Dv,    g_Dv);
    cudaGetSymbolAddress((void**)&p_DA,    g_DA);
    cudaGetSymbolAddress((void**)&p_stats, g_stats);
    auto SB = [&](int i) { return p_stats + (size_t)i * 512; };

    const int GF = (NFC + 63) / 64;   // 157
    const int GN = (NV  + 63) / 64;   // 79
    const int GS = (NNZT * 8 + 255) / 256;
    const float INV_F = 1.0f / (float)NFC;
    const float INV_N = 1.0f / (float)NV;

    cudaMemsetAsync(p_stats, 0, (size_t)64 * 512 * sizeof(float));
    cudaMemsetAsync(p_ef, 0, (size_t)NFC * 128 * sizeof(float));
    k_in<<<128, 128>>>(inputs, W_in, b_in, SB(1));

    for (int i = 0; i < LAYERS; i++) {
        const float* W0i  = W0  + (size_t)i * 256 * 128;
        const float* Wl1i = Wl1 + (size_t)i * 256 * 128;
        int c1 = 2 * i, c2 = 2 * i + 1;
        if ((i & 1) == 0) {
            cudaMemsetAsync(p_Dv, 0, (size_t)NFC * 128 * sizeof(float));
            k_spmm<<<GS, 256>>>(Di_rows, Di_cols, Di_vals, p_ev, p_Dv);
            k_stats128<<<256, 128>>>(p_Dv, NFC, SB(c1), 128);
            k_gemm<16, false><<<GF, 256>>>(p_ef, p_Dv, NFC, W0i, b0 + i * 128,
                                           g0 + i * 256, be0 + i * 256, SB(c1), INV_F,
                                           nullptr, p_ef, SB(c1 + 4));
            cudaMemsetAsync(p_DA, 0, (size_t)NV * 128 * sizeof(float));
            k_spmm<<<GS, 256>>>(DiA_rows, DiA_cols, DiA_vals, p_ef, p_DA);
            k_stats128<<<256, 128>>>(p_DA, NV, SB(c2), 128);
            k_gemm<16, true><<<GN, 256>>>(p_ev, p_DA, NV, Wl1i, bl1 + i * 128,
                                          g1 + i * 256, be1 + i * 256, SB(c2), INV_N,
                                          p_v, p_ev, SB(c2 + 1));
        } else {
            k_gemm<8, false><<<GN, 256>>>(p_ev, nullptr, NV, W0i, b0 + i * 128,
                                          g0 + i * 256, be0 + i * 256, SB(c1), INV_N,
                                          nullptr, p_ex, SB(c1 + 1));
            k_gemm<8, true><<<GN, 256>>>(p_ex, nullptr, NV, Wl1i, bl1 + i * 128,
                                         g1 + i * 256, be1 + i * 256, SB(c2), INV_N,
                                         p_v, p_ev, SB(c2 + 2));
        }
    }

    k_stats128<<<256, 128>>>(p_v, NV, SB(62), 0);
    k_head_prep<<<1, 128>>>(g2, be2, W_out, b_out, SB(62), INV_N);
    k_final<<<(NV * 32 + 255) / 256, 256>>>(W_out, out);
}

// round 9
// speedup vs baseline: 1.4822x; 1.4822x over previous
#include <cuda_runtime.h>
#include <math.h>

// Problem constants
#define NV    5000
#define NFC   10000
#define LAYERS 30
#define NNZT  480000
#define EPSBN 1e-5f

// ---------------- device scratch ----------------
__device__ __align__(16) float g_v [NV  * 128];
__device__ __align__(16) float g_ev[NV  * 128];
__device__ __align__(16) float g_ef[NFC * 128];
__device__ __align__(16) float g_ex[NV  * 128];
__device__ __align__(16) float g_Dv[NFC * 128];
__device__ __align__(16) float g_DA[NV  * 128];
__device__ float g_stats[64 * 512];
__device__ float g_a   [128];
__device__ float g_bout[1];

__device__ __forceinline__ float eluf(float x) {
    return x > 0.f ? x : (__expf(x) - 1.f);
}

// ---------------- input projection ----------------
__global__ void k_in(const float* __restrict__ in, const float* __restrict__ Wi,
                     const float* __restrict__ bi, float* __restrict__ statp) {
    int c = threadIdx.x;  // 128
    float w0 = Wi[c], w1 = Wi[128 + c], w2 = Wi[256 + c], b = bi[c];
    float s = 0.f, s2 = 0.f;
    for (int n = blockIdx.x; n < NV; n += gridDim.x) {
        float val = b + in[n * 3] * w0 + in[n * 3 + 1] * w1 + in[n * 3 + 2] * w2;
        g_v [n * 128 + c] = val;
        float e = eluf(val);
        g_ev[n * 128 + c] = e;
        s += e; s2 += e * e;
    }
    atomicAdd(&statp[c], s);
    atomicAdd(&statp[256 + c], s2);
}

// ---------------- COO spMM: 8 threads/edge, float4 vector atomics ----------------
__global__ void k_spmm(const int* __restrict__ rows_, const int* __restrict__ cols_,
                       const float* __restrict__ vals,
                       const float* __restrict__ X, float* __restrict__ Y) {
    int idx = blockIdx.x * blockDim.x + threadIdx.x;
    int e = idx >> 3, d = idx & 7;
    if (e >= NNZT) return;
    int R = rows_[e], Cq = cols_[e];
    float v = vals[e];
    float4 xv = ((const float4*)X)[(Cq >> 2) * 32 + (Cq & 3) * 8 + d];
    float4* yp = (float4*)Y + (R >> 2) * 32 + (R & 3) * 8 + d;
    asm volatile("red.global.add.v4.f32 [%0], {%1,%2,%3,%4};"
                 :: "l"(yp), "f"(v * xv.x), "f"(v * xv.y), "f"(v * xv.z), "f"(v * xv.w)
                 : "memory");
}

// ---------------- column stats over a [rows,128] tensor ----------------
__global__ void k_stats128(const float* __restrict__ X, int rows,
                           float* __restrict__ statp, int off) {
    int c = threadIdx.x;  // 128
    float s = 0.f, s2 = 0.f;
    for (int r = blockIdx.x; r < rows; r += gridDim.x) {
        float x = X[r * 128 + c];
        s += x; s2 += x * x;
    }
    atomicAdd(&statp[off + c], s);
    atomicAdd(&statp[256 + off + c], s2);
}

// ---------------- fused BN + bias-fold + GEMM + elu + stats (col-split x2) -------
// Each CTA: 64 rows x 64 cols (blockIdx.y selects column half). Double-buffered.
// out = (A*a) @ W + bias [+ V];  A = [L | R] split pointers, each [rows,128]
template<int KT, bool ACC>
__global__ void __launch_bounds__(256)
k_gemm(const float* __restrict__ L, const float* __restrict__ R, int rows,
       const float* __restrict__ W, const float* __restrict__ bvec,
       const float* __restrict__ gamma, const float* __restrict__ beta,
       const float* __restrict__ statp_in, float invn,
       float* __restrict__ Vout, float* __restrict__ Eout,
       float* __restrict__ statp_out) {
    __shared__ __align__(16) float As[2][16][72];
    __shared__ __align__(16) float Bs[2][16][72];
    __shared__ float sSc[256];
    __shared__ float sT [256];
    __shared__ float sB [64];
    int tid = threadIdx.x;  // 256
    int col0 = blockIdx.y * 64;

    // prologue: BN fold (redundant per block)
    if (KT == 16 || tid < 128) {
        float mean = statp_in[tid] * invn;
        float var  = fmaxf(statp_in[256 + tid] * invn - mean * mean, 0.f);
        float a = gamma[tid] * rsqrtf(var + EPSBN);
        sSc[tid] = a;
        sT[tid]  = beta[tid] - mean * a;
    } else {
        sT[tid] = beta[tid];   // broadcast-avg columns: var==0 -> BN out == beta
    }
    __syncthreads();

    int row0 = blockIdx.x * 64;
    int wc = tid & 31, wr = tid >> 5;   // outputs: rows wr*8+i, cols col0 + wc*2 + j
    float acc[8][2];
#pragma unroll
    for (int i = 0; i < 8; i++) { acc[i][0] = 0.f; acc[i][1] = 0.f; }
    float biasAcc = 0.f;

    int am = tid >> 2, ak4 = (tid & 3) * 4;   // A loader: 64 rows x 16 k (all 256 thr)
    int bk = tid >> 4, bc = (tid & 15) * 4;   // B loader: 16 rows x 64 cols
    float4 rA, rB;

    auto loadRegs = [&](int t) {
        int k0 = t * 16;
        const float* Ab = (KT == 16 && k0 >= 128) ? R : L;
        int r = row0 + am;
        rA = make_float4(0.f, 0.f, 0.f, 0.f);
        if (r < rows) rA = *(const float4*)&Ab[r * 128 + (k0 & 127) + ak4];
        rB = *(const float4*)&W[(k0 + bk) * 128 + col0 + bc];
    };
    auto storeSmem = [&](int t, int b) {
        int k0 = t * 16;
        As[b][ak4 + 0][am] = rA.x * sSc[k0 + ak4 + 0];
        As[b][ak4 + 1][am] = rA.y * sSc[k0 + ak4 + 1];
        As[b][ak4 + 2][am] = rA.z * sSc[k0 + ak4 + 2];
        As[b][ak4 + 3][am] = rA.w * sSc[k0 + ak4 + 3];
        *(float4*)&Bs[b][bk][bc] = rB;
    };

    loadRegs(0);
    storeSmem(0, 0);
    __syncthreads();
#pragma unroll 1
    for (int t = 0; t < KT; t++) {
        int b = t & 1;
        if (t + 1 < KT) loadRegs(t + 1);   // prefetch hides LDG latency
        if (tid < 64) {                     // bias fold on resident W tile
            int k0 = t * 16;
#pragma unroll
            for (int k = 0; k < 16; k++) biasAcc += sT[k0 + k] * Bs[b][k][tid];
        }
#pragma unroll
        for (int k = 0; k < 16; k++) {
            float4 a0 = *(const float4*)&As[b][k][wr * 8];
            float4 a1 = *(const float4*)&As[b][k][wr * 8 + 4];
            float2 b2 = *(const float2*)&Bs[b][k][wc * 2];
            acc[0][0] += a0.x * b2.x; acc[0][1] += a0.x * b2.y;
            acc[1][0] += a0.y * b2.x; acc[1][1] += a0.y * b2.y;
            acc[2][0] += a0.z * b2.x; acc[2][1] += a0.z * b2.y;
            acc[3][0] += a0.w * b2.x; acc[3][1] += a0.w * b2.y;
            acc[4][0] += a1.x * b2.x; acc[4][1] += a1.x * b2.y;
            acc[5][0] += a1.y * b2.x; acc[5][1] += a1.y * b2.y;
            acc[6][0] += a1.z * b2.x; acc[6][1] += a1.z * b2.y;
            acc[7][0] += a1.w * b2.x; acc[7][1] += a1.w * b2.y;
        }
        if (t + 1 < KT) storeSmem(t + 1, b ^ 1);
        __syncthreads();
    }

    // KT==8: bias contribution of folded-away W rows 128..255 (t = beta there)
    if (KT == 8 && tid < 64) {
#pragma unroll 4
        for (int c = 128; c < 256; c++) biasAcc += sT[c] * W[c * 128 + col0 + tid];
    }
    if (tid < 64) sB[tid] = biasAcc + bvec[col0 + tid];
    __syncthreads();

    // epilogue: bias (+accum), elu, per-column stats
    float s1v[2] = {0.f, 0.f};
    float s2v[2] = {0.f, 0.f};
#pragma unroll
    for (int i = 0; i < 8; i++) {
        int r = row0 + wr * 8 + i;
        if (r >= rows) continue;
        int C = col0 + wc * 2;
        float v0 = acc[i][0] + sB[wc * 2];
        float v1 = acc[i][1] + sB[wc * 2 + 1];
        if (ACC) {
            float2 old = *(float2*)&Vout[r * 128 + C];
            v0 += old.x; v1 += old.y;
            *(float2*)&Vout[r * 128 + C] = make_float2(v0, v1);
        }
        float e0 = eluf(v0), e1 = eluf(v1);
        *(float2*)&Eout[r * 128 + C] = make_float2(e0, e1);
        s1v[0] += e0; s1v[1] += e1;
        s2v[0] += e0 * e0; s2v[1] += e1 * e1;
    }
    float* red1 = &As[0][0][0];   // 8 warps x 64 cols
    float* red2 = &As[1][0][0];
    red1[wr * 64 + wc * 2]     = s1v[0];
    red1[wr * 64 + wc * 2 + 1] = s1v[1];
    red2[wr * 64 + wc * 2]     = s2v[0];
    red2[wr * 64 + wc * 2 + 1] = s2v[1];
    __syncthreads();
    if (tid < 64) {
        float s = 0.f;
#pragma unroll
        for (int w = 0; w < 8; w++) s += red1[w * 64 + tid];
        atomicAdd(&statp_out[col0 + tid], s);
    } else if (tid < 128) {
        int c = tid - 64;
        float s = 0.f;
#pragma unroll
        for (int w = 0; w < 8; w++) s += red2[w * 64 + c];
        atomicAdd(&statp_out[256 + col0 + c], s);
    }
}

// ---------------- final head ----------------
__global__ void k_head_prep(const float* __restrict__ gamma, const float* __restrict__ beta,
                            const float* __restrict__ Wout, const float* __restrict__ bout,
                            const float* __restrict__ statp, float invn) {
    __shared__ float sh[128];
    int c = threadIdx.x;  // 128
    float mean = statp[c] * invn;
    float var  = fmaxf(statp[256 + c] * invn - mean * mean, 0.f);
    float a = gamma[c] * rsqrtf(var + EPSBN);
    g_a[c] = a;
    sh[c] = (beta[c] - mean * a) * Wout[c];
    __syncthreads();
    for (int s = 64; s > 0; s >>= 1) {
        if (c < s) sh[c] += sh[c + s];
        __syncthreads();
    }
    if (c == 0) g_bout[0] = bout[0] + sh[0];
}

__global__ void k_final(const float* __restrict__ Wout, float* __restrict__ out) {
    int warp = (blockIdx.x * blockDim.x + threadIdx.x) >> 5;
    int lane = threadIdx.x & 31;
    if (warp >= NV) return;
    float s = 0.f;
#pragma unroll
    for (int q = 0; q < 4; q++) {
        int c = q * 32 + lane;
        s += g_v[warp * 128 + c] * g_a[c] * Wout[c];
    }
#pragma unroll
    for (int o = 16; o; o >>= 1) s += __shfl_xor_sync(0xffffffffu, s, o);
    if (lane == 0) out[warp] = eluf(s + g_bout[0]);
}

// ---------------- host orchestration ----------------
extern "C" void kernel_launch(void* const* d_in, const int* in_sizes, int n_in,
                              void* d_out, int out_size) {
    const float* inputs   = (const float*)d_in[0];
    const int*   Di_rows  = (const int*)d_in[2];
    const int*   Di_cols  = (const int*)d_in[3];
    const float* Di_vals  = (const float*)d_in[4];
    const int*   DiA_rows = (const int*)d_in[5];
    const int*   DiA_cols = (const int*)d_in[6];
    const float* DiA_vals = (const float*)d_in[7];
    const float* W_in  = (const float*)d_in[8];
    const float* b_in  = (const float*)d_in[9];
    const float* g0    = (const float*)d_in[10];
    const float* be0   = (const float*)d_in[11];
    const float* W0    = (const float*)d_in[12];
    const float* b0    = (const float*)d_in[13];
    const float* g1    = (const float*)d_in[14];
    const float* be1   = (const float*)d_in[15];
    const float* Wl1   = (const float*)d_in[16];
    const float* bl1   = (const float*)d_in[17];
    const float* g2    = (const float*)d_in[18];
    const float* be2   = (const float*)d_in[19];
    const float* W_out = (const float*)d_in[20];
    const float* b_out = (const float*)d_in[21];
    float* out = (float*)d_out;
    (void)in_sizes; (void)n_in; (void)out_size;

    float *p_v, *p_ev, *p_ef, *p_ex, *p_Dv, *p_DA, *p_stats;
    cudaGetSymbolAddress((void**)&p_v,     g_v);
    cudaGetSymbolAddress((void**)&p_ev,    g_ev);
    cudaGetSymbolAddress((void**)&p_ef,    g_ef);
    cudaGetSymbolAddress((void**)&p_ex,    g_ex);
    cudaGetSymbolAddress((void**)&p_Dv,    g_Dv);
    cudaGetSymbolAddress((void**)&p_DA,    g_DA);
    cudaGetSymbolAddress((void**)&p_stats, g_stats);
    auto SB = [&](int i) { return p_stats + (size_t)i * 512; };

    const dim3 GF((NFC + 63) / 64, 2);   // 157 x 2 = 314 CTAs
    const dim3 GN((NV  + 63) / 64, 2);   // 79 x 2 = 158 CTAs
    const int GS = (NNZT * 8 + 255) / 256;
    const float INV_F = 1.0f / (float)NFC;
    const float INV_N = 1.0f / (float)NV;

    cudaMemsetAsync(p_stats, 0, (size_t)64 * 512 * sizeof(float));
    cudaMemsetAsync(p_ef, 0, (size_t)NFC * 128 * sizeof(float));
    k_in<<<128, 128>>>(inputs, W_in, b_in, SB(1));

    for (int i = 0; i < LAYERS; i++) {
        const float* W0i  = W0  + (size_t)i * 256 * 128;
        const float* Wl1i = Wl1 + (size_t)i * 256 * 128;
        int c1 = 2 * i, c2 = 2 * i + 1;
        if ((i & 1) == 0) {
            cudaMemsetAsync(p_Dv, 0, (size_t)NFC * 128 * sizeof(float));
            k_spmm<<<GS, 256>>>(Di_rows, Di_cols, Di_vals, p_ev, p_Dv);
            k_stats128<<<256, 128>>>(p_Dv, NFC, SB(c1), 128);
            k_gemm<16, false><<<GF, 256>>>(p_ef, p_Dv, NFC, W0i, b0 + i * 128,
                                           g0 + i * 256, be0 + i * 256, SB(c1), INV_F,
                                           nullptr, p_ef, SB(c1 + 4));
            cudaMemsetAsync(p_DA, 0, (size_t)NV * 128 * sizeof(float));
            k_spmm<<<GS, 256>>>(DiA_rows, DiA_cols, DiA_vals, p_ef, p_DA);
            k_stats128<<<256, 128>>>(p_DA, NV, SB(c2), 128);
            k_gemm<16, true><<<GN, 256>>>(p_ev, p_DA, NV, Wl1i, bl1 + i * 128,
                                          g1 + i * 256, be1 + i * 256, SB(c2), INV_N,
                                          p_v, p_ev, SB(c2 + 1));
        } else {
            k_gemm<8, false><<<GN, 256>>>(p_ev, nullptr, NV, W0i, b0 + i * 128,
                                          g0 + i * 256, be0 + i * 256, SB(c1), INV_N,
                                          nullptr, p_ex, SB(c1 + 1));
            k_gemm<8, true><<<GN, 256>>>(p_ex, nullptr, NV, Wl1i, bl1 + i * 128,
                                         g1 + i * 256, be1 + i * 256, SB(c2), INV_N,
                                         p_v, p_ev, SB(c2 + 2));
        }
    }

    k_stats128<<<256, 128>>>(p_v, NV, SB(62), 0);
    k_head_prep<<<1, 128>>>(g2, be2, W_out, b_out, SB(62), INV_N);
    k_final<<<(NV * 32 + 255) / 256, 256>>>(W_out, out);
}